// round 11
// baseline (speedup 1.0000x reference)
#include <cuda_runtime.h>
#include <cuda_bf16.h>
#include <cstdint>

// ---------------- constants ----------------
#define BATCH 4
#define T_TOTAL 35968706LL          // sum of all hypernet parameter counts
#define T2 (T_TOTAL / 2)            // 17,984,353 float2 columns (T_TOTAL is even)

// ---------------- device scratch (no allocation allowed) ----------------
__device__ float g_bufA[4 * 4 * 112 * 112];   // 200,704 floats
__device__ float g_bufB[4 * 8 * 56 * 56];     // 100,352 floats
__device__ float g_q[BATCH * 16];             // quantized latents for the big GEMM

// ---------------- conv: 4x4 stride-2 pad-1, reduction split over (ci,kh) rows ----
// Reduction dim = CIN*4 rows of 4 taps. SPLIT adjacent lanes each take
// NR/SPLIT rows, then butterfly-reduce. SPLIT is a power of 2 <= 32, and every
// stage TOTAL is an exact multiple of 256 -> no bounds guard, no divergence.
template<int CIN, int COUT, int HIN, int HOUT, bool ACT, int SPLIT, int TPB>
__global__ void __launch_bounds__(TPB) convS(const float* __restrict__ in,
                                             const float* __restrict__ w,
                                             const float* __restrict__ bias,
                                             float* __restrict__ out) {
    constexpr int NR  = CIN * 4;        // (ci, kh) rows
    constexpr int RPT = NR / SPLIT;     // rows per thread
    static_assert(NR % SPLIT == 0, "SPLIT must divide CIN*4");

    int tid = blockIdx.x * TPB + threadIdx.x;
    int s = tid % SPLIT;                // reduction slice (adjacent lanes)
    int o = tid / SPLIT;                // output index
    int ow = o % HOUT;
    int oh = (o / HOUT) % HOUT;
    int co = (o / (HOUT * HOUT)) % COUT;
    int b  = o / (HOUT * HOUT * COUT);

    float acc = 0.0f;
    int ih0 = oh * 2 - 1;
    int iw0 = ow * 2 - 1;

    #pragma unroll
    for (int rr = 0; rr < RPT; rr++) {
        int r  = s * RPT + rr;
        int ci = r >> 2;
        int kh = r & 3;
        int ih = ih0 + kh;
        bool rowok = (unsigned)ih < (unsigned)HIN;
        const float* ip = in + ((size_t)(b * CIN + ci) * HIN + ih) * HIN;
        const float* wp = w + ((size_t)(co * CIN + ci) * 16) + kh * 4;
        #pragma unroll
        for (int kw = 0; kw < 4; kw++) {
            int iw = iw0 + kw;
            bool ok = rowok && ((unsigned)iw < (unsigned)HIN);
            float v = ok ? __ldg(ip + iw) : 0.0f;
            acc = fmaf(v, __ldg(wp + kw), acc);
        }
    }

    // butterfly reduction across the SPLIT slices (adjacent lanes)
    #pragma unroll
    for (int off = SPLIT / 2; off > 0; off >>= 1)
        acc += __shfl_xor_sync(0xffffffffu, acc, off);

    if (s == 0) {
        acc += bias[co];
        if (ACT) acc = (acc >= 0.0f) ? acc : 0.01f * acc;
        out[o] = acc;
    }
}

// ---------------- head: avgpool + fc1 + fc2 + VQ + loss ----------------
// conv5 output (bias applied, no activation): [b][c][49]
__global__ void head_k(const float* __restrict__ conv5,
                       const float* __restrict__ fc1_w, const float* __restrict__ fc1_b,
                       const float* __restrict__ fc2_w, const float* __restrict__ fc2_b,
                       const float* __restrict__ emb,
                       float* __restrict__ loss_out) {
    __shared__ float pooled[BATCH * 64];
    __shared__ float h[BATCH * 16];
    __shared__ float e[BATCH * 16];
    __shared__ float qv[BATCH * 16];
    int tid = threadIdx.x;   // 256 threads

    {
        int b = tid / 64, c = tid % 64;
        const float* p = conv5 + (size_t)(b * 64 + c) * 49;
        float sum = 0.0f;
        #pragma unroll
        for (int i = 0; i < 49; i++) sum += p[i];
        pooled[b * 64 + c] = sum * (1.0f / 49.0f);
    }
    __syncthreads();

    if (tid < 64) {
        int b = tid / 16, i = tid % 16;
        float s = fc1_b[i];
        #pragma unroll
        for (int c = 0; c < 64; c++) s += pooled[b * 64 + c] * fc1_w[i * 64 + c];
        h[b * 16 + i] = (s >= 0.0f) ? s : 0.01f * s;
    }
    __syncthreads();

    if (tid < 64) {
        int b = tid / 16, j = tid % 16;
        float s = fc2_b[j];
        #pragma unroll
        for (int i = 0; i < 16; i++) s += h[b * 16 + i] * fc2_w[j * 16 + i];
        e[b * 16 + j] = s;
    }
    __syncthreads();

    if (tid < BATCH) {
        int b = tid;
        float best = 3.402823e38f;
        int bi = 0;
        for (int j = 0; j < 4; j++) {
            float d = 0.0f;
            #pragma unroll
            for (int k = 0; k < 16; k++) {
                float diff = e[b * 16 + k] - emb[j * 16 + k];
                d += diff * diff;
            }
            if (d < best) { best = d; bi = j; }
        }
        #pragma unroll
        for (int k = 0; k < 16; k++) qv[b * 16 + k] = emb[bi * 16 + k];
    }
    __syncthreads();

    if (tid == 0) {
        float s = 0.0f;
        #pragma unroll
        for (int n = 0; n < 64; n++) {
            float d = qv[n] - e[n];
            s += d * d;
        }
        *loss_out = 1.25f * (s * (1.0f / 64.0f));   // q_lat + 0.25 * e_lat
        #pragma unroll
        for (int n = 0; n < 64; n++) g_q[n] = qv[n];
    }
}

// ---------------- big GEMM: flat = q @ W_all, [4,16] x [16, T_TOTAL] ----------------
// Pure HBM streaming, float2 vectorized, streaming cache hints.
// Measured R9: 396.9 us @ DRAM=90.7%, 7.19 TB/s — do not touch.
__global__ void __launch_bounds__(256) hyper_gemm_k(const float* __restrict__ W,
                                                    float* __restrict__ out) {
    __shared__ float qs[64];
    if (threadIdx.x < 64) qs[threadIdx.x] = g_q[threadIdx.x];
    __syncthreads();

    long long t2 = (long long)blockIdx.x * blockDim.x + threadIdx.x;
    if (t2 >= T2) return;

    float2 w[16];
    #pragma unroll
    for (int k = 0; k < 16; k++) {
        w[k] = __ldcs((const float2*)(W + (size_t)k * T_TOTAL) + t2);
    }

    #pragma unroll
    for (int b = 0; b < 4; b++) {
        float ax = 0.0f, ay = 0.0f;
        #pragma unroll
        for (int k = 0; k < 16; k++) {
            float qk = qs[b * 16 + k];
            ax = fmaf(qk, w[k].x, ax);
            ay = fmaf(qk, w[k].y, ay);
        }
        __stcs((float2*)(out + (size_t)b * T_TOTAL) + t2, make_float2(ax, ay));
    }
}

// ---------------- launch ----------------
extern "C" void kernel_launch(void* const* d_in, const int* in_sizes, int n_in,
                              void* d_out, int out_size) {
    const float* rgb   = (const float*)d_in[0];
    const float* cw1   = (const float*)d_in[1];
    const float* cb1   = (const float*)d_in[2];
    const float* cw2   = (const float*)d_in[3];
    const float* cb2   = (const float*)d_in[4];
    const float* cw3   = (const float*)d_in[5];
    const float* cb3   = (const float*)d_in[6];
    const float* cw4   = (const float*)d_in[7];
    const float* cb4   = (const float*)d_in[8];
    const float* cw5   = (const float*)d_in[9];
    const float* cb5   = (const float*)d_in[10];
    const float* fc1_w = (const float*)d_in[11];
    const float* fc1_b = (const float*)d_in[12];
    const float* fc2_w = (const float*)d_in[13];
    const float* fc2_b = (const float*)d_in[14];
    const float* emb   = (const float*)d_in[15];
    const float* W_all = (const float*)d_in[16];

    float* out = (float*)d_out;
    float* loss_ptr = out + (size_t)out_size - 1;   // flat first, loss scalar last

    float* bufA;  cudaGetSymbolAddress((void**)&bufA, g_bufA);
    float* bufB;  cudaGetSymbolAddress((void**)&bufB, g_bufB);

    // conv1: 3->4, 224->112, NR=12, SPLIT=4  -> 802,816 threads (3136 blocks)
    convS<3, 4, 224, 112, true, 4, 256><<<3136, 256>>>(rgb, cw1, cb1, bufA);
    // conv2: 4->8, 112->56, NR=16, SPLIT=8  -> 802,816 threads
    convS<4, 8, 112, 56, true, 8, 256><<<3136, 256>>>(bufA, cw2, cb2, bufB);
    // conv3: 8->16, 56->28, NR=32, SPLIT=16 -> 802,816 threads
    convS<8, 16, 56, 28, true, 16, 256><<<3136, 256>>>(bufB, cw3, cb3, bufA);
    // conv4: 16->32, 28->14, NR=64, SPLIT=32 -> 802,816 threads
    convS<16, 32, 28, 14, true, 32, 256><<<3136, 256>>>(bufA, cw4, cb4, bufB);
    // conv5: 32->64, 14->7, NR=128, SPLIT=32 -> 401,408 threads, NO act
    convS<32, 64, 14, 7, false, 32, 256><<<1568, 256>>>(bufB, cw5, cb5, bufA);

    // head: pool + fc1 + fc2 + VQ + loss -> writes g_q and loss
    head_k<<<1, 256>>>(bufA, fc1_w, fc1_b, fc2_w, fc2_b, emb, loss_ptr);

    // big streaming GEMM: flat = q @ W_all
    { const int TPB = 256;
      long long nblk = (T2 + TPB - 1) / TPB;
      hyper_gemm_k<<<(unsigned)nblk, TPB>>>(W_all, out); }
}

// round 12
// speedup vs baseline: 1.0224x; 1.0224x over previous
#include <cuda_runtime.h>
#include <cuda_bf16.h>
#include <cstdint>

// ---------------- constants ----------------
#define BATCH 4
#define T_TOTAL 35968706LL          // sum of all hypernet parameter counts
#define T2 (T_TOTAL / 2)            // 17,984,353 float2 columns (T_TOTAL is even)

// ---------------- device scratch (no allocation allowed) ----------------
__device__ float g_bufA[4 * 4 * 112 * 112];   // 200,704 floats
__device__ float g_bufB[4 * 8 * 56 * 56];     // 100,352 floats
__device__ float g_q[BATCH * 16];             // quantized latents for the big GEMM

// ---------------- register-blocked conv: 4x4 stride-2 pad-1 ----------------
// Each thread computes OWB consecutive ow outputs for one (b, co, oh), with the
// (ci,kh) row reduction split across SPLIT adjacent lanes (butterfly reduce).
// Per row: load SPAN=2*OWB+2 input floats once (independent loads, MLP=SPAN),
// one float4 weight load, then 4*OWB FMA reusing registers.
// All grids are exact (TOTAL % 256 == 0): no guards, shuffles full-warp safe.
template<int CIN, int COUT, int HIN, int HOUT, bool ACT, int SPLIT, int OWB, int TPB>
__global__ void __launch_bounds__(TPB) convR(const float* __restrict__ in,
                                             const float* __restrict__ w,
                                             const float* __restrict__ bias,
                                             float* __restrict__ out) {
    constexpr int NR   = CIN * 4;          // (ci, kh) reduction rows
    constexpr int RPT  = NR / SPLIT;       // rows per thread
    constexpr int NOWG = HOUT / OWB;       // ow groups per output row
    constexpr int SPAN = 2 * OWB + 2;      // input cols covering OWB outputs
    static_assert(NR % SPLIT == 0, "SPLIT must divide CIN*4");
    static_assert(HOUT % OWB == 0, "OWB must divide HOUT");

    int tid = blockIdx.x * TPB + threadIdx.x;
    int s   = tid % SPLIT;
    int o   = tid / SPLIT;
    int owg = o % NOWG;
    int oh  = (o / NOWG) % HOUT;
    int co  = (o / (NOWG * HOUT)) % COUT;
    int b   = o / (NOWG * HOUT * COUT);

    int ow0 = owg * OWB;
    int ix0 = 2 * ow0 - 1;                 // leftmost input col (may be -1)

    float acc[OWB];
    #pragma unroll
    for (int j = 0; j < OWB; j++) acc[j] = 0.0f;

    #pragma unroll
    for (int rr = 0; rr < RPT; rr++) {
        int r  = s * RPT + rr;
        int ci = r >> 2;
        int kh = r & 3;
        int ih = 2 * oh - 1 + kh;
        bool rowok = (unsigned)ih < (unsigned)HIN;

        const float* ip = in + ((size_t)(b * CIN + ci) * HIN + ih) * HIN;
        float4 wv = *(const float4*)(w + ((size_t)(co * CIN + ci) * 16) + kh * 4);

        float xv[SPAN];
        #pragma unroll
        for (int x = 0; x < SPAN; x++) {
            int iw = ix0 + x;
            bool ok = rowok && ((unsigned)iw < (unsigned)HIN);
            xv[x] = ok ? __ldg(ip + iw) : 0.0f;
        }

        #pragma unroll
        for (int j = 0; j < OWB; j++) {
            acc[j] = fmaf(xv[2 * j + 0], wv.x, acc[j]);
            acc[j] = fmaf(xv[2 * j + 1], wv.y, acc[j]);
            acc[j] = fmaf(xv[2 * j + 2], wv.z, acc[j]);
            acc[j] = fmaf(xv[2 * j + 3], wv.w, acc[j]);
        }
    }

    // butterfly reduction across the SPLIT adjacent lanes
    #pragma unroll
    for (int off = SPLIT / 2; off > 0; off >>= 1) {
        #pragma unroll
        for (int j = 0; j < OWB; j++)
            acc[j] += __shfl_xor_sync(0xffffffffu, acc[j], off);
    }

    if (s == 0) {
        float bv = bias[co];
        size_t obase = ((size_t)(b * COUT + co) * HOUT + oh) * HOUT + ow0;
        #pragma unroll
        for (int j = 0; j < OWB; j++) {
            float v = acc[j] + bv;
            if (ACT) v = (v >= 0.0f) ? v : 0.01f * v;
            out[obase + j] = v;
        }
    }
}

// ---------------- head: avgpool + fc1 + fc2 + VQ + loss ----------------
// conv5 output (bias applied, no activation): [b][c][49]
__global__ void head_k(const float* __restrict__ conv5,
                       const float* __restrict__ fc1_w, const float* __restrict__ fc1_b,
                       const float* __restrict__ fc2_w, const float* __restrict__ fc2_b,
                       const float* __restrict__ emb,
                       float* __restrict__ loss_out) {
    __shared__ float pooled[BATCH * 64];
    __shared__ float h[BATCH * 16];
    __shared__ float e[BATCH * 16];
    __shared__ float qv[BATCH * 16];
    int tid = threadIdx.x;   // 256 threads

    {
        int b = tid / 64, c = tid % 64;
        const float* p = conv5 + (size_t)(b * 64 + c) * 49;
        float sum = 0.0f;
        #pragma unroll
        for (int i = 0; i < 49; i++) sum += p[i];
        pooled[b * 64 + c] = sum * (1.0f / 49.0f);
    }
    __syncthreads();

    if (tid < 64) {
        int b = tid / 16, i = tid % 16;
        float s = fc1_b[i];
        #pragma unroll
        for (int c = 0; c < 64; c++) s += pooled[b * 64 + c] * fc1_w[i * 64 + c];
        h[b * 16 + i] = (s >= 0.0f) ? s : 0.01f * s;
    }
    __syncthreads();

    if (tid < 64) {
        int b = tid / 16, j = tid % 16;
        float s = fc2_b[j];
        #pragma unroll
        for (int i = 0; i < 16; i++) s += h[b * 16 + i] * fc2_w[j * 16 + i];
        e[b * 16 + j] = s;
    }
    __syncthreads();

    if (tid < BATCH) {
        int b = tid;
        float best = 3.402823e38f;
        int bi = 0;
        for (int j = 0; j < 4; j++) {
            float d = 0.0f;
            #pragma unroll
            for (int k = 0; k < 16; k++) {
                float diff = e[b * 16 + k] - emb[j * 16 + k];
                d += diff * diff;
            }
            if (d < best) { best = d; bi = j; }
        }
        #pragma unroll
        for (int k = 0; k < 16; k++) qv[b * 16 + k] = emb[bi * 16 + k];
    }
    __syncthreads();

    if (tid == 0) {
        float s = 0.0f;
        #pragma unroll
        for (int n = 0; n < 64; n++) {
            float d = qv[n] - e[n];
            s += d * d;
        }
        *loss_out = 1.25f * (s * (1.0f / 64.0f));   // q_lat + 0.25 * e_lat
        #pragma unroll
        for (int n = 0; n < 64; n++) g_q[n] = qv[n];
    }
}

// ---------------- big GEMM: flat = q @ W_all, [4,16] x [16, T_TOTAL] ----------------
// Pure HBM streaming, float2 vectorized, streaming cache hints.
// Measured R9: 396.9 us @ DRAM=90.7%, 7.19 TB/s — do not touch.
__global__ void __launch_bounds__(256) hyper_gemm_k(const float* __restrict__ W,
                                                    float* __restrict__ out) {
    __shared__ float qs[64];
    if (threadIdx.x < 64) qs[threadIdx.x] = g_q[threadIdx.x];
    __syncthreads();

    long long t2 = (long long)blockIdx.x * blockDim.x + threadIdx.x;
    if (t2 >= T2) return;

    float2 w[16];
    #pragma unroll
    for (int k = 0; k < 16; k++) {
        w[k] = __ldcs((const float2*)(W + (size_t)k * T_TOTAL) + t2);
    }

    #pragma unroll
    for (int b = 0; b < 4; b++) {
        float ax = 0.0f, ay = 0.0f;
        #pragma unroll
        for (int k = 0; k < 16; k++) {
            float qk = qs[b * 16 + k];
            ax = fmaf(qk, w[k].x, ax);
            ay = fmaf(qk, w[k].y, ay);
        }
        __stcs((float2*)(out + (size_t)b * T_TOTAL) + t2, make_float2(ax, ay));
    }
}

// ---------------- launch ----------------
extern "C" void kernel_launch(void* const* d_in, const int* in_sizes, int n_in,
                              void* d_out, int out_size) {
    const float* rgb   = (const float*)d_in[0];
    const float* cw1   = (const float*)d_in[1];
    const float* cb1   = (const float*)d_in[2];
    const float* cw2   = (const float*)d_in[3];
    const float* cb2   = (const float*)d_in[4];
    const float* cw3   = (const float*)d_in[5];
    const float* cb3   = (const float*)d_in[6];
    const float* cw4   = (const float*)d_in[7];
    const float* cb4   = (const float*)d_in[8];
    const float* cw5   = (const float*)d_in[9];
    const float* cb5   = (const float*)d_in[10];
    const float* fc1_w = (const float*)d_in[11];
    const float* fc1_b = (const float*)d_in[12];
    const float* fc2_w = (const float*)d_in[13];
    const float* fc2_b = (const float*)d_in[14];
    const float* emb   = (const float*)d_in[15];
    const float* W_all = (const float*)d_in[16];

    float* out = (float*)d_out;
    float* loss_ptr = out + (size_t)out_size - 1;   // flat first, loss scalar last

    float* bufA;  cudaGetSymbolAddress((void**)&bufA, g_bufA);
    float* bufB;  cudaGetSymbolAddress((void**)&bufB, g_bufB);

    // Exact grids: TOTAL = B*COUT*HOUT*(HOUT/OWB)*SPLIT, all multiples of 256.
    // conv1: 3->4, 224->112, SPLIT=4, OWB=8 -> 100,352 thr (392 blocks)
    convR<3, 4, 224, 112, true, 4, 8, 256><<<392, 256>>>(rgb, cw1, cb1, bufA);
    // conv2: 4->8, 112->56, SPLIT=4, OWB=8 -> 50,176 thr (196 blocks)
    convR<4, 8, 112, 56, true, 4, 8, 256><<<196, 256>>>(bufA, cw2, cb2, bufB);
    // conv3: 8->16, 56->28, SPLIT=8, OWB=7 -> 57,344 thr (224 blocks)
    convR<8, 16, 56, 28, true, 8, 7, 256><<<224, 256>>>(bufB, cw3, cb3, bufA);
    // conv4: 16->32, 28->14, SPLIT=16, OWB=7 -> 57,344 thr (224 blocks)
    convR<16, 32, 28, 14, true, 16, 7, 256><<<224, 256>>>(bufA, cw4, cb4, bufB);
    // conv5: 32->64, 14->7, SPLIT=32, OWB=7, NO act -> 57,344 thr (224 blocks)
    convR<32, 64, 14, 7, false, 32, 7, 256><<<224, 256>>>(bufB, cw5, cb5, bufA);

    // head: pool + fc1 + fc2 + VQ + loss -> writes g_q and loss
    head_k<<<1, 256>>>(bufA, fc1_w, fc1_b, fc2_w, fc2_b, emb, loss_ptr);

    // big streaming GEMM: flat = q @ W_all
    { const int TPB = 256;
      long long nblk = (T2 + TPB - 1) / TPB;
      hyper_gemm_k<<<(unsigned)nblk, TPB>>>(W_all, out); }
}